// round 15
// baseline (speedup 1.0000x reference)
#include <cuda_runtime.h>
#include <cuda_bf16.h>
#include <math.h>
#include <stdint.h>

// ---------------- problem constants ----------------
#define B_    512
#define L_    4
#define M_    8
#define N_    64
#define NP1   65
#define POS   520           // M_*NP1
#define FLAT  33280         // 64*POS
#define ROWS  2048          // B_*L_
#define JD    256           // pl1 out
#define J2D   128           // pl2 out

#define SPLIT 9             // q-splits (144 CTAs on 148 SMs)
#define RPJ   (SPLIT * JD)  // 2304 per-row partial stride
#define BCH   16384         // B chunk words (64 k x 256 j)

// output layout: W (512*80) | Theta (2048*64*2) | mu (512*2)
#define OFF_THETA 40960
#define OFF_MU    (40960 + 262144)

// ---------------- scratch ----------------
__device__ float g_Bw2[(size_t)POS * BCH];            // pl1_w permuted [q][o][j] (tf32)
__device__ float g_Bw[(size_t)POS * BCH];             // frag-packed B
__device__ float g_xT[(size_t)ROWS * POS * 8];        // x transposed: [bl][q][c] (fp32)
__device__ float g_Rpart[(size_t)ROWS * RPJ];         // split-K partials [row][sp][j]
__device__ float g_pl2T[JD * J2D];                    // pl2_w transposed

// ---------------- helpers ----------------
__device__ __forceinline__ uint32_t to_tf32(float v) {
    uint32_t u;
    asm("cvt.rna.tf32.f32 %0, %1;" : "=r"(u) : "f"(v));
    return u;
}
__device__ __forceinline__ void split_tf32(uint32_t v, uint32_t& hi, uint32_t& lo) {
    float f = __uint_as_float(v);
    uint32_t h = to_tf32(f);
    float fl = f - __uint_as_float(h);
    hi = h;
    lo = to_tf32(fl);
}
__device__ __forceinline__ uint32_t pack_bf16x2(float a, float b) {
    __nv_bfloat162 h = __floats2bfloat162_rn(a, b);
    return *(uint32_t*)&h;
}
__device__ __forceinline__ uint32_t smem_u32(const void* p) {
    uint32_t a;
    asm("{ .reg .u64 t; cvta.to.shared.u64 t, %1; cvt.u32.u64 %0, t; }" : "=r"(a) : "l"(p));
    return a;
}
#define CPASYNC16(sa, gp)  asm volatile("cp.async.cg.shared.global [%0], [%1], 16;" :: "r"(sa), "l"(gp) : "memory")
#define CP_COMMIT()        asm volatile("cp.async.commit_group;" ::: "memory")
#define CP_WAIT0()         asm volatile("cp.async.wait_group 0;" ::: "memory")
#define BAR_GROUP(id)      asm volatile("bar.sync %0, 128;" :: "r"(id) : "memory")

__device__ __forceinline__ void mma_tf32(float* d, const uint32_t* a, const uint32_t* b) {
    asm volatile(
        "mma.sync.aligned.m16n8k8.row.col.f32.tf32.tf32.f32 "
        "{%0,%1,%2,%3}, {%4,%5,%6,%7}, {%8,%9}, {%0,%1,%2,%3};"
        : "+f"(d[0]), "+f"(d[1]), "+f"(d[2]), "+f"(d[3])
        : "r"(a[0]), "r"(a[1]), "r"(a[2]), "r"(a[3]), "r"(b[0]), "r"(b[1]));
}
__device__ __forceinline__ void mma_bf16(float* d, const uint32_t* a, const uint32_t* b) {
    asm volatile(
        "mma.sync.aligned.m16n8k16.row.col.f32.bf16.bf16.f32 "
        "{%0,%1,%2,%3}, {%4,%5,%6,%7}, {%8,%9}, {%0,%1,%2,%3};"
        : "+f"(d[0]), "+f"(d[1]), "+f"(d[2]), "+f"(d[3])
        : "r"(a[0]), "r"(a[1]), "r"(a[2]), "r"(a[3]), "r"(b[0]), "r"(b[1]));
}
__device__ __forceinline__ void ldsm_x4(uint32_t* r, uint32_t addr) {
    asm volatile("ldmatrix.sync.aligned.m8n8.x4.shared.b16 {%0,%1,%2,%3}, [%4];"
        : "=r"(r[0]), "=r"(r[1]), "=r"(r[2]), "=r"(r[3]) : "r"(addr));
}

// ---------------- K0: transpose pl2_w (128x256 -> 256x128) ----------------
__global__ void k0_transpose(const float* __restrict__ pl2_w) {
    int idx = blockIdx.x * 256 + threadIdx.x;
    int i = idx >> 7;
    int j = idx & 127;
    g_pl2T[idx] = pl2_w[j * JD + i];
}

// ---------------- K0x: x -> xq[bl][q][c], raw fp32 ----------------
__global__ void __launch_bounds__(256) k0x(const float* __restrict__ x) {
    int tl = blockIdx.x * 256 + threadIdx.x;
    int bl = tl / POS;
    int q  = tl - bl * POS;
    const float* xp = x + (size_t)bl * (8 * POS) + q;
    float4 v0, v1;
    v0.x = xp[0 * POS]; v0.y = xp[1 * POS]; v0.z = xp[2 * POS]; v0.w = xp[3 * POS];
    v1.x = xp[4 * POS]; v1.y = xp[5 * POS]; v1.z = xp[6 * POS]; v1.w = xp[7 * POS];
    float4* dst = (float4*)(g_xT + (size_t)tl * 8);
    dst[0] = v0;
    dst[1] = v1;
}

// ---------------- K0p: permute pl1_w [j][k] -> old layout [q][o][j], tf32 ----
__global__ void __launch_bounds__(256) k0p(const float* __restrict__ pl1_w) {
    __shared__ float ts[32][33];
    int k0 = blockIdx.x * 32;
    int j0 = blockIdx.y * 32;
    int tx = threadIdx.x & 31;
    int ty = threadIdx.x >> 5;
#pragma unroll
    for (int r = 0; r < 4; r++) {
        int j = j0 + ty + r * 8;
        ts[ty + r * 8][tx] = pl1_w[(size_t)j * FLAT + k0 + tx];
    }
    __syncthreads();
#pragma unroll
    for (int r = 0; r < 4; r++) {
        int k = k0 + ty + r * 8;
        int o = k / POS;
        int q = k - o * POS;
        g_Bw2[((size_t)q * 64 + o) * JD + j0 + tx] =
            __uint_as_float(to_tf32(ts[tx][ty + r * 8]));
    }
}

// ---------------- K0p2: old layout -> fragment layout -----------------------
#define BSP 264
__global__ void __launch_bounds__(256) k0p2() {
    __shared__ float bs[8 * BSP];
    int q  = blockIdx.x;
    int ks = blockIdx.y;
    int tid = threadIdx.x;
    const float* src = g_Bw2 + (size_t)q * BCH + ks * 2048;
#pragma unroll
    for (int i = tid; i < 2048; i += 256) {
        int o = i >> 8, j = i & 255;
        bs[o * BSP + j] = src[i];
    }
    __syncthreads();
    float4* dst = (float4*)(g_Bw + (size_t)q * BCH + ks * 2048);
#pragma unroll
    for (int u = tid; u < 512; u += 256) {
        int jt2 = u >> 5, lane = u & 31;
        int ob = lane & 3;
        int jb = jt2 * 16 + (lane >> 2);
        float4 o4;
        o4.x = bs[ob * BSP + jb];
        o4.y = bs[(ob + 4) * BSP + jb];
        o4.z = bs[ob * BSP + jb + 8];
        o4.w = bs[(ob + 4) * BSP + jb + 8];
        dst[u] = o4;
    }
}

// ---------------- KF: fused conv1+conv2+pl1 GEMM (512 thr, 16 warps) ----
// Warp quads own 32 rows: conv warp-pair per m16 tile (nt-halves), main
// warp tile 32x64 (4x4 grid). acc=64 regs -> fits 128 regs/thread.
#define AS_STRIDE 68
#define AS_FLOATS (128 * AS_STRIDE)      // 8704
#define XS_STRIDE 12
#define XS_FLOATS (128 * XS_STRIDE)      // 1536
#define KF_WORDS (2*BCH + AS_FLOATS + 2*XS_FLOATS + 1024 + 4096 + 128)
#define KF_DYN   (KF_WORDS * 4)          // 199,168 B

__device__ __forceinline__ void kf_load_chunk(
    uint32_t bsA, uint32_t xsA, int q, int row0, int tid)
{
    const float* Bq = g_Bw + (size_t)q * BCH;
#pragma unroll
    for (int k = 0; k < 8; k++) {
        int u = tid + k * 512;
        CPASYNC16(bsA + (uint32_t)u * 16, Bq + (size_t)u * 4);
    }
    if (tid < 256) {
        int r = tid >> 1, half = tid & 1;
        const float* src = g_xT + ((size_t)(row0 + r) * POS + q) * 8 + half * 4;
        CPASYNC16(xsA + (uint32_t)(r * XS_STRIDE + half * 4) * 4, src);
    }
}

__global__ void __launch_bounds__(512, 1) kF(
    const float* __restrict__ w1, const float* __restrict__ b1,
    const float* __restrict__ w2, const float* __restrict__ b2)
{
    extern __shared__ float sm[];
    float*    BsF[2] = { sm, sm + BCH };
    float*    AsF    = sm + 2 * BCH;                           // [128][AS_STRIDE]
    float*    XsF    = AsF + AS_FLOATS;
    uint32_t* W1fh   = (uint32_t*)(XsF + 2 * XS_FLOATS);      // [8 nt][32 lane][2]
    uint32_t* W1fl   = W1fh + 512;
    uint32_t* W2fh   = W1fl + 512;                             // [4 ks][4 ntp][32 lane][4]
    uint32_t* W2fl   = W2fh + 2048;
    float*    b1s    = (float*)(W2fl + 2048);
    float*    b2s    = b1s + 64;

    uint32_t sbase = smem_u32(sm);
    uint32_t bsA[2] = { sbase, sbase + BCH * 4 };
    uint32_t asAaddr = sbase + (uint32_t)(2 * BCH) * 4;
    uint32_t xsA[2] = { sbase + (uint32_t)(2 * BCH + AS_FLOATS) * 4,
                        sbase + (uint32_t)(2 * BCH + AS_FLOATS + XS_FLOATS) * 4 };
    const uint32_t* XsU[2] = { (const uint32_t*)XsF,
                               (const uint32_t*)(XsF + XS_FLOATS) };

    int tid = threadIdx.x;
    int w = tid >> 5, lane = tid & 31, g = lane >> 2, tg = lane & 3;
    int row0 = blockIdx.x * 128;
    int sp = blockIdx.y;
    int q0  = (POS * sp) / SPLIT;
    int qe  = (POS * (sp + 1)) / SPLIT;
    int nch = qe - q0;

    // W1 frags: [nt][lane][w2] (tf32 hi/lo)
    for (int i = tid; i < 512; i += 512) {
        int nt = i >> 6, ln = (i >> 1) & 31, ww = i & 1;
        int g2 = ln >> 2, tg2 = ln & 3;
        int o = nt * 8 + g2, c = tg2 + 4 * ww;
        uint32_t hi, lo;
        split_tf32(__float_as_uint(w1[o * 8 + c]), hi, lo);
        W1fh[i] = hi;
        W1fl[i] = lo;
    }
    // W2 frags: [ks][ntp][lane][w4] (bf16-pair hi/lo)
    for (int i = tid; i < 2048; i += 512) {
        int ks = i >> 9, ntp = (i >> 7) & 3, ln = (i >> 2) & 31, ww = i & 3;
        int g2 = ln >> 2, tg2 = ln & 3;
        int nt = ntp * 2 + (ww >> 1);
        int kp = ks * 8 + tg2 + 4 * (ww & 1);
        int o = nt * 8 + g2;
        float v0 = w2[o * 64 + 2 * kp];
        float v1 = w2[o * 64 + 2 * kp + 1];
        __nv_bfloat16 h0 = __float2bfloat16_rn(v0);
        __nv_bfloat16 h1 = __float2bfloat16_rn(v1);
        W2fh[i] = pack_bf16x2(__bfloat162float(h0), __bfloat162float(h1));
        W2fl[i] = pack_bf16x2(v0 - __bfloat162float(h0), v1 - __bfloat162float(h1));
    }
    if (tid < 64) { b1s[tid] = b1[tid]; b2s[tid] = b2[tid]; }

    kf_load_chunk(bsA[0], xsA[0], q0, row0, tid);
    CP_COMMIT();

    int grp = w >> 2;         // quad: owns rows grp*32..grp*32+31
    int wm  = grp * 32;       // main warp M offset
    int wn  = (w & 3) * 64;   // main warp N offset
    int rt  = w >> 1;         // conv m16 tile (warp pairs share)
    int hf  = w & 1;          // conv nt half
    int m1  = rt * 16;

    int rowA = wm + (lane & 7) + ((lane >> 3) & 1) * 8;
    int colA = (lane >> 4) * 4;
    uint32_t aBase = asAaddr + (uint32_t)(rowA * AS_STRIDE + colA) * 4;

    float acc[2][8][4];
#pragma unroll
    for (int i = 0; i < 2; i++)
#pragma unroll
        for (int j = 0; j < 8; j++)
#pragma unroll
            for (int c = 0; c < 4; c++) acc[i][j][c] = 0.f;

    const uint2* W1fh2 = (const uint2*)W1fh;
    const uint2* W1fl2 = (const uint2*)W1fl;
    const uint4* W2fh4 = (const uint4*)W2fh;
    const uint4* W2fl4 = (const uint4*)W2fl;

    for (int it = 0; it < nch; it++) {
        int cur = it & 1;
        CP_WAIT0();
        __syncthreads();   // Bs/Xs[cur] ready; prev main done with Bs[cur^1]

        if (it + 1 < nch) {
            kf_load_chunk(bsA[cur ^ 1], xsA[cur ^ 1], q0 + it + 1, row0, tid);
            CP_COMMIT();
        }

        // ---- conv1 (tf32x3, full) + conv2 (bf16x3, nt-half) in regs ----
        float s[4][4];
#pragma unroll
        for (int nt = 0; nt < 4; nt++)
#pragma unroll
            for (int c = 0; c < 4; c++) s[nt][c] = 0.f;
        {
            const uint32_t* Xc = XsU[cur];
            uint32_t a[4], xh[4], xl[4];
            a[0] = Xc[(m1 + g) * XS_STRIDE + tg];
            a[1] = Xc[(m1 + g + 8) * XS_STRIDE + tg];
            a[2] = Xc[(m1 + g) * XS_STRIDE + tg + 4];
            a[3] = Xc[(m1 + g + 8) * XS_STRIDE + tg + 4];
#pragma unroll
            for (int t = 0; t < 4; t++) split_tf32(a[t], xh[t], xl[t]);

#pragma unroll
            for (int ks = 0; ks < 4; ks++) {
                uint32_t ah[4], al[4];
#pragma unroll
                for (int h = 0; h < 2; h++) {
                    int nt = 2 * ks + h;
                    uint2 vh = W1fh2[nt * 32 + lane];
                    uint2 vl = W1fl2[nt * 32 + lane];
                    uint32_t bh[2]  = { vh.x, vh.y };
                    uint32_t blo[2] = { vl.x, vl.y };
                    float c[4] = { 0.f, 0.f, 0.f, 0.f };
                    mma_tf32(c, xh, bh);
                    mma_tf32(c, xl, bh);
                    mma_tf32(c, xh, blo);
                    float bb0 = b1s[nt * 8 + 2 * tg], bb1 = b1s[nt * 8 + 2 * tg + 1];
                    float v00 = fmaxf(c[0] + bb0, 0.f);
                    float v01 = fmaxf(c[1] + bb1, 0.f);
                    float v10 = fmaxf(c[2] + bb0, 0.f);
                    float v11 = fmaxf(c[3] + bb1, 0.f);
                    __nv_bfloat16 h00 = __float2bfloat16_rn(v00);
                    __nv_bfloat16 h01 = __float2bfloat16_rn(v01);
                    __nv_bfloat16 h10 = __float2bfloat16_rn(v10);
                    __nv_bfloat16 h11 = __float2bfloat16_rn(v11);
                    ah[2 * h]     = pack_bf16x2(__bfloat162float(h00), __bfloat162float(h01));
                    ah[2 * h + 1] = pack_bf16x2(__bfloat162float(h10), __bfloat162float(h11));
                    al[2 * h]     = pack_bf16x2(v00 - __bfloat162float(h00),
                                                v01 - __bfloat162float(h01));
                    al[2 * h + 1] = pack_bf16x2(v10 - __bfloat162float(h10),
                                                v11 - __bfloat162float(h11));
                }
#pragma unroll
                for (int np = 0; np < 2; np++) {
                    int ntp = hf * 2 + np;
                    uint4 vh = W2fh4[ks * 128 + ntp * 32 + lane];
                    uint4 vl = W2fl4[ks * 128 + ntp * 32 + lane];
                    uint32_t bh0[2] = { vh.x, vh.y }, bh1[2] = { vh.z, vh.w };
                    uint32_t bl0[2] = { vl.x, vl.y }, bl1[2] = { vl.z, vl.w };
                    mma_bf16(s[2 * np],     ah, bh0);
                    mma_bf16(s[2 * np],     al, bh0);
                    mma_bf16(s[2 * np],     ah, bl0);
                    mma_bf16(s[2 * np + 1], ah, bh1);
                    mma_bf16(s[2 * np + 1], al, bh1);
                    mma_bf16(s[2 * np + 1], ah, bl1);
                }
            }
        }

        // ---- store S -> AsF (bias + relu + tf32 round), nt-half ----
#pragma unroll
        for (int ntl = 0; ntl < 4; ntl++) {
            int nt = hf * 4 + ntl;
            float bb0 = b2s[nt * 8 + 2 * tg], bb1 = b2s[nt * 8 + 2 * tg + 1];
            float2 p0, p1;
            p0.x = __uint_as_float(to_tf32(fmaxf(s[ntl][0] + bb0, 0.f)));
            p0.y = __uint_as_float(to_tf32(fmaxf(s[ntl][1] + bb1, 0.f)));
            p1.x = __uint_as_float(to_tf32(fmaxf(s[ntl][2] + bb0, 0.f)));
            p1.y = __uint_as_float(to_tf32(fmaxf(s[ntl][3] + bb1, 0.f)));
            *(float2*)&AsF[(m1 + g) * AS_STRIDE + nt * 8 + 2 * tg] = p0;
            *(float2*)&AsF[(m1 + g + 8) * AS_STRIDE + nt * 8 + 2 * tg] = p1;
        }
        BAR_GROUP(1 + grp);   // quad's 32 As rows complete

        // ---- main: acc += A[32 rows quad] @ Bq[64x64 per warp] ----
        {
            const uint4* Bf4 = (const uint4*)BsF[cur];
            int jbase = (w & 3) * 4;
#pragma unroll
            for (int ks = 0; ks < 8; ks++) {
                uint32_t af[2][4];
#pragma unroll
                for (int im = 0; im < 2; im++)
                    ldsm_x4(af[im], aBase + (uint32_t)(im * 16 * AS_STRIDE) * 4
                                         + (uint32_t)ks * 32);
                uint32_t bfr[8][2];
#pragma unroll
                for (int jp = 0; jp < 4; jp++) {
                    uint4 v = Bf4[ks * 512 + (jbase + jp) * 32 + lane];
                    bfr[2 * jp][0]     = v.x;
                    bfr[2 * jp][1]     = v.y;
                    bfr[2 * jp + 1][0] = v.z;
                    bfr[2 * jp + 1][1] = v.w;
                }
#pragma unroll
                for (int im = 0; im < 2; im++)
#pragma unroll
                    for (int jn = 0; jn < 8; jn++)
                        mma_tf32(acc[im][jn], af[im], bfr[jn]);
            }
        }
    }

    // epilogue: partials at [row][sp][j]
#pragma unroll
    for (int im = 0; im < 2; im++) {
        int r = row0 + wm + im * 16 + g;
#pragma unroll
        for (int jn = 0; jn < 8; jn++) {
            int c = wn + jn * 8 + tg * 2;
            *(float2*)(g_Rpart + (size_t)r * RPJ + sp * JD + c) =
                make_float2(acc[im][jn][0], acc[im][jn][1]);
            *(float2*)(g_Rpart + (size_t)(r + 8) * RPJ + sp * JD + c) =
                make_float2(acc[im][jn][2], acc[im][jn][3]);
        }
    }
}

// ---------------- K34: split-K reduce + pl2 + Theta + head MLPs (fused) -----
__global__ void __launch_bounds__(256) k34(
    const float* __restrict__ pl1_b,
    const float* __restrict__ pl2_b,
    const float* __restrict__ H_re, const float* __restrict__ H_im,
    const float* __restrict__ ch_re, const float* __restrict__ ch_im,
    const float* __restrict__ b1_w, const float* __restrict__ b1_b,
    const float* __restrict__ b2_w, const float* __restrict__ b2_b,
    const float* __restrict__ b3_w, const float* __restrict__ b3_b,
    const float* __restrict__ p1_w, const float* __restrict__ p1_b,
    const float* __restrict__ p2_w, const float* __restrict__ p2_b,
    float* __restrict__ outW, float* __restrict__ outTheta,
    float* __restrict__ outMu)
{
    __shared__ float Hs[4][JD];
    __shared__ float Rls[4][J2D];
    __shared__ float trs[256], tis[256];
    __shared__ float cHs[64], W1s[128], P1s[128], W2s[128], W3s[80];
    __shared__ float MUs[2], SCs[1];

    int b   = blockIdx.x;        // batch = 4 rows
    int r0  = b * 4;
    int tid = threadIdx.x;

    // ---- split-K reduce + bias/relu ----
#pragma unroll
    for (int rr = 0; rr < 4; rr++) {
        const float* p = g_Rpart + (size_t)(r0 + rr) * RPJ + tid;
        float s = 0.f;
#pragma unroll
        for (int sp = 0; sp < SPLIT; sp++)
            s += p[sp * JD];
        Hs[rr][tid] = fmaxf(s + pl1_b[tid], 0.f);
    }
    __syncthreads();

    // ---- pl2 ----
    {
        int j = tid & 127;
        int half = tid >> 7;
        float a0 = pl2_b[j], a1 = a0;
#pragma unroll 8
        for (int i = 0; i < JD; i++) {
            float w = g_pl2T[i * J2D + j];
            a0 += Hs[2 * half][i] * w;
            a1 += Hs[2 * half + 1][i] * w;
        }
        Rls[2 * half][j] = a0;
        Rls[2 * half + 1][j] = a1;
    }
    __syncthreads();

    // ---- Theta (smem + output) ----
    {
        int rr = tid >> 6, n = tid & 63;
        float pr = Rls[rr][n];
        float pi = Rls[rr][n + N_];
        float nm = fmaxf(sqrtf(pr * pr + pi * pi), 1e-12f);
        float tr = pr / nm, ti = pi / nm;
        int r = r0 + rr;
        outTheta[((size_t)r * N_ + n) * 2 + 0] = tr;
        outTheta[((size_t)r * N_ + n) * 2 + 1] = ti;
        trs[tid] = tr;
        tis[tid] = ti;
    }
    __syncthreads();

    // ---- einsum (coalesced) ----
    {
        int w = tid >> 5, lane = tid & 31;
        int kk = lane & 3, l = (lane >> 2) & 3, dn = lane >> 4;
        const float* hre = H_re + (size_t)b * 8192 + w * 1024;
        const float* him = H_im + (size_t)b * 8192 + w * 1024;
        float s_rr = 0.f, s_ii = 0.f, s_ri = 0.f, s_ir = 0.f;
#pragma unroll 4
        for (int ng = 0; ng < 32; ng++) {
            int n = ng * 2 + dn;
            float tr = trs[l * 64 + n];
            float ti = tis[l * 64 + n];
            float hr = hre[ng * 32 + lane];
            float hi = him[ng * 32 + lane];
            s_rr += hr * tr; s_ii += hi * ti;
            s_ri += hr * ti; s_ir += hi * tr;
        }
#pragma unroll
        for (int off = 4; off < 32; off <<= 1) {
            s_rr += __shfl_xor_sync(0xffffffffu, s_rr, off);
            s_ii += __shfl_xor_sync(0xffffffffu, s_ii, off);
            s_ri += __shfl_xor_sync(0xffffffffu, s_ri, off);
            s_ir += __shfl_xor_sync(0xffffffffu, s_ir, off);
        }
        if (lane < 4) {
            cHs[kk * 16 + w]     = s_rr + s_ii + ch_re[(b * 4 + kk) * 8 + w];
            cHs[kk * 16 + 8 + w] = s_ri - s_ir + ch_im[(b * 4 + kk) * 8 + w];
        }
    }
    __syncthreads();

    if (tid < 128) {
        float a = b1_b[tid];
        for (int c = 0; c < 64; c++) a += b1_w[tid * 64 + c] * cHs[c];
        W1s[tid] = fmaxf(a, 0.f);
    } else {
        int jj = tid - 128;
        float a = p1_b[jj];
        for (int c = 0; c < 64; c++) a += p1_w[jj * 64 + c] * cHs[c];
        P1s[jj] = fmaxf(a, 0.f);
    }
    __syncthreads();

    if (tid < 128) {
        float a = b2_b[tid];
        for (int c = 0; c < 128; c++) a += b2_w[tid * 128 + c] * W1s[c];
        W2s[tid] = fmaxf(a, 0.f);
    } else if (tid < 130) {
        int m2 = tid - 128;
        float a = p2_b[m2];
        for (int c = 0; c < 128; c++) a += p2_w[m2 * 128 + c] * P1s[c];
        MUs[m2] = a;
    }
    __syncthreads();

    if (tid < 80) {
        float a = b3_b[tid];
        for (int c = 0; c < 128; c++) a += b3_w[tid * 128 + c] * W2s[c];
        W3s[tid] = a;
    }
    __syncthreads();

    if (tid == 0) {
        float ss = 0.f;
        for (int j = 0; j < 80; j++) ss += W3s[j] * W3s[j];
        float wn = fmaxf(sqrtf(ss), 1e-12f);
        float mx = fmaxf(MUs[0], MUs[1]);
        float e0 = expf(MUs[0] - mx), e1 = expf(MUs[1] - mx);
        float mu0 = e0 / (e0 + e1);
        MUs[0] = mu0;
        MUs[1] = e1 / (e0 + e1);
        SCs[0] = sqrtf(10.0f) * sqrtf(mu0) / wn;
    }
    __syncthreads();

    if (tid < 80) outW[b * 80 + tid] = W3s[tid] * SCs[0];
    if (tid < 2)  outMu[b * 2 + tid] = MUs[tid];
}

// ---------------- launch ----------------
extern "C" void kernel_launch(void* const* d_in, const int* in_sizes, int n_in,
                              void* d_out, int out_size)
{
    const float* x       = (const float*)d_in[0];
    const float* H_re    = (const float*)d_in[1];
    const float* H_im    = (const float*)d_in[2];
    const float* ch_re   = (const float*)d_in[3];
    const float* ch_im   = (const float*)d_in[4];
    const float* conv1_w = (const float*)d_in[5];
    const float* conv1_b = (const float*)d_in[6];
    const float* conv2_w = (const float*)d_in[7];
    const float* conv2_b = (const float*)d_in[8];
    const float* pl1_w   = (const float*)d_in[9];
    const float* pl1_b   = (const float*)d_in[10];
    const float* pl2_w   = (const float*)d_in[11];
    const float* pl2_b   = (const float*)d_in[12];
    const float* b1_w    = (const float*)d_in[13];
    const float* b1_b    = (const float*)d_in[14];
    const float* b2_w    = (const float*)d_in[15];
    const float* b2_b    = (const float*)d_in[16];
    const float* b3_w    = (const float*)d_in[17];
    const float* b3_b    = (const float*)d_in[18];
    const float* p1_w    = (const float*)d_in[19];
    const float* p1_b    = (const float*)d_in[20];
    const float* p2_w    = (const float*)d_in[21];
    const float* p2_b    = (const float*)d_in[22];

    float* out      = (float*)d_out;
    float* outW     = out;
    float* outTheta = out + OFF_THETA;
    float* outMu    = out + OFF_MU;

    cudaFuncSetAttribute(kF, cudaFuncAttributeMaxDynamicSharedMemorySize, KF_DYN);

    k0_transpose<<<128, 256>>>(pl2_w);
    k0x<<<(ROWS * POS) / 256, 256>>>(x);
    dim3 gp(FLAT / 32, JD / 32);
    k0p<<<gp, 256>>>(pl1_w);
    dim3 gp2(POS, 8);
    k0p2<<<gp2, 256>>>();
    dim3 gf(ROWS / 128, SPLIT);
    kF<<<gf, 512, KF_DYN>>>(conv1_w, conv1_b, conv2_w, conv2_b);
    k34<<<B_, 256>>>(pl1_b, pl2_b, H_re, H_im, ch_re, ch_im,
                     b1_w, b1_b, b2_w, b2_b, b3_w, b3_b,
                     p1_w, p1_b, p2_w, p2_b, outW, outTheta, outMu);
}

// round 16
// speedup vs baseline: 1.0235x; 1.0235x over previous
#include <cuda_runtime.h>
#include <cuda_bf16.h>
#include <math.h>
#include <stdint.h>

// ---------------- problem constants ----------------
#define B_    512
#define L_    4
#define M_    8
#define N_    64
#define NP1   65
#define POS   520           // M_*NP1
#define FLAT  33280         // 64*POS
#define ROWS  2048          // B_*L_
#define JD    256           // pl1 out
#define J2D   128           // pl2 out

#define SPLIT 9             // q-splits (144 CTAs on 148 SMs)
#define RPJ   (SPLIT * JD)  // 2304 per-row partial stride
#define BCH   16384         // B chunk words (64 k x 256 j)

// output layout: W (512*80) | Theta (2048*64*2) | mu (512*2)
#define OFF_THETA 40960
#define OFF_MU    (40960 + 262144)

// ---------------- scratch ----------------
__device__ float g_Bw2[(size_t)POS * BCH];            // pl1_w permuted [q][o][j] (tf32)
__device__ float g_Bw[(size_t)POS * BCH];             // frag-packed B
__device__ float g_xT[(size_t)ROWS * POS * 8];        // x transposed: [bl][q][c] (fp32)
__device__ float g_Rpart[(size_t)ROWS * RPJ];         // split-K partials [row][sp][j]
__device__ float g_pl2T[JD * J2D];                    // pl2_w transposed

// ---------------- helpers ----------------
__device__ __forceinline__ uint32_t to_tf32(float v) {
    uint32_t u;
    asm("cvt.rna.tf32.f32 %0, %1;" : "=r"(u) : "f"(v));
    return u;
}
__device__ __forceinline__ void split_tf32(uint32_t v, uint32_t& hi, uint32_t& lo) {
    float f = __uint_as_float(v);
    uint32_t h = to_tf32(f);
    float fl = f - __uint_as_float(h);
    hi = h;
    lo = to_tf32(fl);
}
__device__ __forceinline__ uint32_t pack_bf16x2(float a, float b) {
    __nv_bfloat162 h = __floats2bfloat162_rn(a, b);
    return *(uint32_t*)&h;
}
__device__ __forceinline__ uint32_t smem_u32(const void* p) {
    uint32_t a;
    asm("{ .reg .u64 t; cvta.to.shared.u64 t, %1; cvt.u32.u64 %0, t; }" : "=r"(a) : "l"(p));
    return a;
}
#define CPASYNC16(sa, gp)  asm volatile("cp.async.cg.shared.global [%0], [%1], 16;" :: "r"(sa), "l"(gp) : "memory")
#define CP_COMMIT()        asm volatile("cp.async.commit_group;" ::: "memory")
#define CP_WAIT0()         asm volatile("cp.async.wait_group 0;" ::: "memory")
#define BAR_GROUP(id)      asm volatile("bar.sync %0, 128;" :: "r"(id) : "memory")

__device__ __forceinline__ void mma_tf32(float* d, const uint32_t* a, const uint32_t* b) {
    asm volatile(
        "mma.sync.aligned.m16n8k8.row.col.f32.tf32.tf32.f32 "
        "{%0,%1,%2,%3}, {%4,%5,%6,%7}, {%8,%9}, {%0,%1,%2,%3};"
        : "+f"(d[0]), "+f"(d[1]), "+f"(d[2]), "+f"(d[3])
        : "r"(a[0]), "r"(a[1]), "r"(a[2]), "r"(a[3]), "r"(b[0]), "r"(b[1]));
}
__device__ __forceinline__ void mma_bf16(float* d, const uint32_t* a, const uint32_t* b) {
    asm volatile(
        "mma.sync.aligned.m16n8k16.row.col.f32.bf16.bf16.f32 "
        "{%0,%1,%2,%3}, {%4,%5,%6,%7}, {%8,%9}, {%0,%1,%2,%3};"
        : "+f"(d[0]), "+f"(d[1]), "+f"(d[2]), "+f"(d[3])
        : "r"(a[0]), "r"(a[1]), "r"(a[2]), "r"(a[3]), "r"(b[0]), "r"(b[1]));
}
__device__ __forceinline__ void ldsm_x4(uint32_t* r, uint32_t addr) {
    asm volatile("ldmatrix.sync.aligned.m8n8.x4.shared.b16 {%0,%1,%2,%3}, [%4];"
        : "=r"(r[0]), "=r"(r[1]), "=r"(r[2]), "=r"(r[3]) : "r"(addr));
}

// ---------------- K0: transpose pl2_w (128x256 -> 256x128) ----------------
__global__ void k0_transpose(const float* __restrict__ pl2_w) {
    int idx = blockIdx.x * 256 + threadIdx.x;
    int i = idx >> 7;
    int j = idx & 127;
    g_pl2T[idx] = pl2_w[j * JD + i];
}

// ---------------- K0x: x -> xq[bl][q][c], raw fp32 ----------------
__global__ void __launch_bounds__(256) k0x(const float* __restrict__ x) {
    int tl = blockIdx.x * 256 + threadIdx.x;
    int bl = tl / POS;
    int q  = tl - bl * POS;
    const float* xp = x + (size_t)bl * (8 * POS) + q;
    float4 v0, v1;
    v0.x = xp[0 * POS]; v0.y = xp[1 * POS]; v0.z = xp[2 * POS]; v0.w = xp[3 * POS];
    v1.x = xp[4 * POS]; v1.y = xp[5 * POS]; v1.z = xp[6 * POS]; v1.w = xp[7 * POS];
    float4* dst = (float4*)(g_xT + (size_t)tl * 8);
    dst[0] = v0;
    dst[1] = v1;
}

// ---------------- K0p: permute pl1_w [j][k] -> old layout [q][o][j], tf32 ----
__global__ void __launch_bounds__(256) k0p(const float* __restrict__ pl1_w) {
    __shared__ float ts[32][33];
    int k0 = blockIdx.x * 32;
    int j0 = blockIdx.y * 32;
    int tx = threadIdx.x & 31;
    int ty = threadIdx.x >> 5;
#pragma unroll
    for (int r = 0; r < 4; r++) {
        int j = j0 + ty + r * 8;
        ts[ty + r * 8][tx] = pl1_w[(size_t)j * FLAT + k0 + tx];
    }
    __syncthreads();
#pragma unroll
    for (int r = 0; r < 4; r++) {
        int k = k0 + ty + r * 8;
        int o = k / POS;
        int q = k - o * POS;
        g_Bw2[((size_t)q * 64 + o) * JD + j0 + tx] =
            __uint_as_float(to_tf32(ts[tx][ty + r * 8]));
    }
}

// ---------------- K0p2: old layout -> fragment layout -----------------------
#define BSP 264
__global__ void __launch_bounds__(256) k0p2() {
    __shared__ float bs[8 * BSP];
    int q  = blockIdx.x;
    int ks = blockIdx.y;
    int tid = threadIdx.x;
    const float* src = g_Bw2 + (size_t)q * BCH + ks * 2048;
#pragma unroll
    for (int i = tid; i < 2048; i += 256) {
        int o = i >> 8, j = i & 255;
        bs[o * BSP + j] = src[i];
    }
    __syncthreads();
    float4* dst = (float4*)(g_Bw + (size_t)q * BCH + ks * 2048);
#pragma unroll
    for (int u = tid; u < 512; u += 256) {
        int jt2 = u >> 5, lane = u & 31;
        int ob = lane & 3;
        int jb = jt2 * 16 + (lane >> 2);
        float4 o4;
        o4.x = bs[ob * BSP + jb];
        o4.y = bs[(ob + 4) * BSP + jb];
        o4.z = bs[ob * BSP + jb + 8];
        o4.w = bs[(ob + 4) * BSP + jb + 8];
        dst[u] = o4;
    }
}

// ---------------- KF: fused conv1+conv2+pl1 GEMM (256 thr, frag-packed) ----
// Row-split warp groups: warps 0-3 own rows 0-63, warps 4-7 rows 64-127.
#define AS_STRIDE 68
#define AS_FLOATS (128 * AS_STRIDE)      // 8704
#define XS_STRIDE 12
#define XS_FLOATS (128 * XS_STRIDE)      // 1536
#define KF_WORDS (2*BCH + AS_FLOATS + 2*XS_FLOATS + 1024 + 4096 + 128)
#define KF_DYN   (KF_WORDS * 4)          // 199,168 B

__device__ __forceinline__ void kf_load_chunk(
    uint32_t bsA, uint32_t xsA, int q, int row0, int tid)
{
    const float* Bq = g_Bw + (size_t)q * BCH;
#pragma unroll
    for (int k = 0; k < 16; k++) {
        int u = tid + k * 256;
        CPASYNC16(bsA + (uint32_t)u * 16, Bq + (size_t)u * 4);
    }
    {
        int r = tid >> 1, half = tid & 1;
        const float* src = g_xT + ((size_t)(row0 + r) * POS + q) * 8 + half * 4;
        CPASYNC16(xsA + (uint32_t)(r * XS_STRIDE + half * 4) * 4, src);
    }
}

__global__ void __launch_bounds__(256, 1) kF(
    const float* __restrict__ w1, const float* __restrict__ b1,
    const float* __restrict__ w2, const float* __restrict__ b2)
{
    extern __shared__ float sm[];
    float*    BsF[2] = { sm, sm + BCH };
    float*    AsF    = sm + 2 * BCH;                           // [128][AS_STRIDE]
    float*    XsF    = AsF + AS_FLOATS;
    uint32_t* W1fh   = (uint32_t*)(XsF + 2 * XS_FLOATS);      // [8 nt][32 lane][2]
    uint32_t* W1fl   = W1fh + 512;
    uint32_t* W2fh   = W1fl + 512;                             // [4 ks][4 ntp][32 lane][4]
    uint32_t* W2fl   = W2fh + 2048;
    float*    b1s    = (float*)(W2fl + 2048);
    float*    b2s    = b1s + 64;

    uint32_t sbase = smem_u32(sm);
    uint32_t bsA[2] = { sbase, sbase + BCH * 4 };
    uint32_t asAaddr = sbase + (uint32_t)(2 * BCH) * 4;
    uint32_t xsA[2] = { sbase + (uint32_t)(2 * BCH + AS_FLOATS) * 4,
                        sbase + (uint32_t)(2 * BCH + AS_FLOATS + XS_FLOATS) * 4 };
    const uint32_t* XsU[2] = { (const uint32_t*)XsF,
                               (const uint32_t*)(XsF + XS_FLOATS) };

    int tid = threadIdx.x;
    int w = tid >> 5, lane = tid & 31, g = lane >> 2, tg = lane & 3;
    int grp = w >> 2;          // warp group: rows grp*64..grp*64+63
    int row0 = blockIdx.x * 128;
    int sp = blockIdx.y;
    int q0  = (POS * sp) / SPLIT;
    int qe  = (POS * (sp + 1)) / SPLIT;
    int nch = qe - q0;

    // W1 frags: [nt][lane][w2] (tf32 hi/lo)
    for (int i = tid; i < 512; i += 256) {
        int nt = i >> 6, ln = (i >> 1) & 31, ww = i & 1;
        int g2 = ln >> 2, tg2 = ln & 3;
        int o = nt * 8 + g2, c = tg2 + 4 * ww;
        uint32_t hi, lo;
        split_tf32(__float_as_uint(w1[o * 8 + c]), hi, lo);
        W1fh[i] = hi;
        W1fl[i] = lo;
    }
    // W2 frags: [ks][ntp][lane][w4] (bf16-pair hi/lo)
    for (int i = tid; i < 2048; i += 256) {
        int ks = i >> 9, ntp = (i >> 7) & 3, ln = (i >> 2) & 31, ww = i & 3;
        int g2 = ln >> 2, tg2 = ln & 3;
        int nt = ntp * 2 + (ww >> 1);
        int kp = ks * 8 + tg2 + 4 * (ww & 1);
        int o = nt * 8 + g2;
        float v0 = w2[o * 64 + 2 * kp];
        float v1 = w2[o * 64 + 2 * kp + 1];
        __nv_bfloat16 h0 = __float2bfloat16_rn(v0);
        __nv_bfloat16 h1 = __float2bfloat16_rn(v1);
        W2fh[i] = pack_bf16x2(__bfloat162float(h0), __bfloat162float(h1));
        W2fl[i] = pack_bf16x2(v0 - __bfloat162float(h0), v1 - __bfloat162float(h1));
    }
    if (tid < 64) { b1s[tid] = b1[tid]; b2s[tid] = b2[tid]; }

    kf_load_chunk(bsA[0], xsA[0], q0, row0, tid);
    CP_COMMIT();

    int wm = grp * 64;        // main warp M offset (group-owned rows)
    int wn = (w & 3) * 64;
    int m1 = w * 16;          // conv row tile

    int rowA = wm + (lane & 7) + ((lane >> 3) & 1) * 8;
    int colA = (lane >> 4) * 4;
    uint32_t aBase = asAaddr + (uint32_t)(rowA * AS_STRIDE + colA) * 4;

    float acc[4][8][4];
#pragma unroll
    for (int i = 0; i < 4; i++)
#pragma unroll
        for (int j = 0; j < 8; j++)
#pragma unroll
            for (int c = 0; c < 4; c++) acc[i][j][c] = 0.f;

    const uint2* W1fh2 = (const uint2*)W1fh;
    const uint2* W1fl2 = (const uint2*)W1fl;
    const uint4* W2fh4 = (const uint4*)W2fh;
    const uint4* W2fl4 = (const uint4*)W2fl;

    for (int it = 0; it < nch; it++) {
        int cur = it & 1;
        CP_WAIT0();
        __syncthreads();   // Bs/Xs[cur] ready; prev main done with Bs[cur^1]

        if (it + 1 < nch) {
            kf_load_chunk(bsA[cur ^ 1], xsA[cur ^ 1], q0 + it + 1, row0, tid);
            CP_COMMIT();
        }

        // ---- conv1 (tf32x3) + conv2 (bf16x3), register-resident ----
        float s[8][4];
#pragma unroll
        for (int nt = 0; nt < 8; nt++)
#pragma unroll
            for (int c = 0; c < 4; c++) s[nt][c] = 0.f;
        {
            const uint32_t* Xc = XsU[cur];
            uint32_t a[4], xh[4], xl[4];
            a[0] = Xc[(m1 + g) * XS_STRIDE + tg];
            a[1] = Xc[(m1 + g + 8) * XS_STRIDE + tg];
            a[2] = Xc[(m1 + g) * XS_STRIDE + tg + 4];
            a[3] = Xc[(m1 + g + 8) * XS_STRIDE + tg + 4];
#pragma unroll
            for (int t = 0; t < 4; t++) split_tf32(a[t], xh[t], xl[t]);

#pragma unroll
            for (int ks = 0; ks < 4; ks++) {
                uint32_t ah[4], al[4];
#pragma unroll
                for (int h = 0; h < 2; h++) {
                    int nt = 2 * ks + h;
                    uint2 vh = W1fh2[nt * 32 + lane];
                    uint2 vl = W1fl2[nt * 32 + lane];
                    uint32_t bh[2]  = { vh.x, vh.y };
                    uint32_t blo[2] = { vl.x, vl.y };
                    float c[4] = { 0.f, 0.f, 0.f, 0.f };
                    mma_tf32(c, xh, bh);
                    mma_tf32(c, xl, bh);
                    mma_tf32(c, xh, blo);
                    float bb0 = b1s[nt * 8 + 2 * tg], bb1 = b1s[nt * 8 + 2 * tg + 1];
                    float v00 = fmaxf(c[0] + bb0, 0.f);
                    float v01 = fmaxf(c[1] + bb1, 0.f);
                    float v10 = fmaxf(c[2] + bb0, 0.f);
                    float v11 = fmaxf(c[3] + bb1, 0.f);
                    __nv_bfloat16 h00 = __float2bfloat16_rn(v00);
                    __nv_bfloat16 h01 = __float2bfloat16_rn(v01);
                    __nv_bfloat16 h10 = __float2bfloat16_rn(v10);
                    __nv_bfloat16 h11 = __float2bfloat16_rn(v11);
                    ah[2 * h]     = pack_bf16x2(__bfloat162float(h00), __bfloat162float(h01));
                    ah[2 * h + 1] = pack_bf16x2(__bfloat162float(h10), __bfloat162float(h11));
                    al[2 * h]     = pack_bf16x2(v00 - __bfloat162float(h00),
                                                v01 - __bfloat162float(h01));
                    al[2 * h + 1] = pack_bf16x2(v10 - __bfloat162float(h10),
                                                v11 - __bfloat162float(h11));
                }
#pragma unroll
                for (int ntp = 0; ntp < 4; ntp++) {
                    uint4 vh = W2fh4[ks * 128 + ntp * 32 + lane];
                    uint4 vl = W2fl4[ks * 128 + ntp * 32 + lane];
                    uint32_t bh0[2] = { vh.x, vh.y }, bh1[2] = { vh.z, vh.w };
                    uint32_t bl0[2] = { vl.x, vl.y }, bl1[2] = { vl.z, vl.w };
                    mma_bf16(s[2 * ntp],     ah, bh0);
                    mma_bf16(s[2 * ntp],     al, bh0);
                    mma_bf16(s[2 * ntp],     ah, bl0);
                    mma_bf16(s[2 * ntp + 1], ah, bh1);
                    mma_bf16(s[2 * ntp + 1], al, bh1);
                    mma_bf16(s[2 * ntp + 1], ah, bl1);
                }
            }
        }

        // ---- store S -> AsF (bias + relu + tf32 round), group-local rows ----
#pragma unroll
        for (int nt = 0; nt < 8; nt++) {
            float bb0 = b2s[nt * 8 + 2 * tg], bb1 = b2s[nt * 8 + 2 * tg + 1];
            float2 p0, p1;
            p0.x = __uint_as_float(to_tf32(fmaxf(s[nt][0] + bb0, 0.f)));
            p0.y = __uint_as_float(to_tf32(fmaxf(s[nt][1] + bb1, 0.f)));
            p1.x = __uint_as_float(to_tf32(fmaxf(s[nt][2] + bb0, 0.f)));
            p1.y = __uint_as_float(to_tf32(fmaxf(s[nt][3] + bb1, 0.f)));
            *(float2*)&AsF[(m1 + g) * AS_STRIDE + nt * 8 + 2 * tg] = p0;
            *(float2*)&AsF[(m1 + g + 8) * AS_STRIDE + nt * 8 + 2 * tg] = p1;
        }
        BAR_GROUP(1 + grp);   // group's As rows complete; groups may skew

        // ---- main: acc += A[64x64 group rows] @ Bq[64x256] ----
        {
            const uint4* Bf4 = (const uint4*)BsF[cur];
            int jbase = (w & 3) * 4;
#pragma unroll
            for (int ks = 0; ks < 8; ks++) {
                uint32_t af[4][4];
#pragma unroll
                for (int im = 0; im < 4; im++)
                    ldsm_x4(af[im], aBase + (uint32_t)(im * 16 * AS_STRIDE) * 4
                                         + (uint32_t)ks * 32);
                uint32_t bfr[8][2];
#pragma unroll
                for (int jp = 0; jp < 4; jp++) {
                    uint4 v = Bf4[ks * 512 + (jbase + jp) * 32 + lane];
                    bfr[2 * jp][0]     = v.x;
                    bfr[2 * jp][1]     = v.y;
                    bfr[2 * jp + 1][0] = v.z;
                    bfr[2 * jp + 1][1] = v.w;
                }
#pragma unroll
                for (int im = 0; im < 4; im++)
#pragma unroll
                    for (int jn = 0; jn < 8; jn++)
                        mma_tf32(acc[im][jn], af[im], bfr[jn]);
            }
        }
    }

    // epilogue: partials at [row][sp][j]
#pragma unroll
    for (int im = 0; im < 4; im++) {
        int r = row0 + wm + im * 16 + g;
#pragma unroll
        for (int jn = 0; jn < 8; jn++) {
            int c = wn + jn * 8 + tg * 2;
            *(float2*)(g_Rpart + (size_t)r * RPJ + sp * JD + c) =
                make_float2(acc[im][jn][0], acc[im][jn][1]);
            *(float2*)(g_Rpart + (size_t)(r + 8) * RPJ + sp * JD + c) =
                make_float2(acc[im][jn][2], acc[im][jn][3]);
        }
    }
}

// ---------------- K34: split-K reduce + pl2 + Theta + head MLPs (fused) -----
__global__ void __launch_bounds__(256) k34(
    const float* __restrict__ pl1_b,
    const float* __restrict__ pl2_b,
    const float* __restrict__ H_re, const float* __restrict__ H_im,
    const float* __restrict__ ch_re, const float* __restrict__ ch_im,
    const float* __restrict__ b1_w, const float* __restrict__ b1_b,
    const float* __restrict__ b2_w, const float* __restrict__ b2_b,
    const float* __restrict__ b3_w, const float* __restrict__ b3_b,
    const float* __restrict__ p1_w, const float* __restrict__ p1_b,
    const float* __restrict__ p2_w, const float* __restrict__ p2_b,
    float* __restrict__ outW, float* __restrict__ outTheta,
    float* __restrict__ outMu)
{
    __shared__ float Hs[4][JD];
    __shared__ float Rls[4][J2D];
    __shared__ float trs[256], tis[256];
    __shared__ float cHs[64], W1s[128], P1s[128], W2s[128], W3s[80];
    __shared__ float MUs[2], SCs[1];

    int b   = blockIdx.x;        // batch = 4 rows
    int r0  = b * 4;
    int tid = threadIdx.x;

    // ---- split-K reduce + bias/relu ----
#pragma unroll
    for (int rr = 0; rr < 4; rr++) {
        const float* p = g_Rpart + (size_t)(r0 + rr) * RPJ + tid;
        float s = 0.f;
#pragma unroll
        for (int sp = 0; sp < SPLIT; sp++)
            s += p[sp * JD];
        Hs[rr][tid] = fmaxf(s + pl1_b[tid], 0.f);
    }
    __syncthreads();

    // ---- pl2 ----
    {
        int j = tid & 127;
        int half = tid >> 7;
        float a0 = pl2_b[j], a1 = a0;
#pragma unroll 8
        for (int i = 0; i < JD; i++) {
            float w = g_pl2T[i * J2D + j];
            a0 += Hs[2 * half][i] * w;
            a1 += Hs[2 * half + 1][i] * w;
        }
        Rls[2 * half][j] = a0;
        Rls[2 * half + 1][j] = a1;
    }
    __syncthreads();

    // ---- Theta (smem + output) ----
    {
        int rr = tid >> 6, n = tid & 63;
        float pr = Rls[rr][n];
        float pi = Rls[rr][n + N_];
        float nm = fmaxf(sqrtf(pr * pr + pi * pi), 1e-12f);
        float tr = pr / nm, ti = pi / nm;
        int r = r0 + rr;
        outTheta[((size_t)r * N_ + n) * 2 + 0] = tr;
        outTheta[((size_t)r * N_ + n) * 2 + 1] = ti;
        trs[tid] = tr;
        tis[tid] = ti;
    }
    __syncthreads();

    // ---- einsum (coalesced) ----
    {
        int w = tid >> 5, lane = tid & 31;
        int kk = lane & 3, l = (lane >> 2) & 3, dn = lane >> 4;
        const float* hre = H_re + (size_t)b * 8192 + w * 1024;
        const float* him = H_im + (size_t)b * 8192 + w * 1024;
        float s_rr = 0.f, s_ii = 0.f, s_ri = 0.f, s_ir = 0.f;
#pragma unroll 4
        for (int ng = 0; ng < 32; ng++) {
            int n = ng * 2 + dn;
            float tr = trs[l * 64 + n];
            float ti = tis[l * 64 + n];
            float hr = hre[ng * 32 + lane];
            float hi = him[ng * 32 + lane];
            s_rr += hr * tr; s_ii += hi * ti;
            s_ri += hr * ti; s_ir += hi * tr;
        }
#pragma unroll
        for (int off = 4; off < 32; off <<= 1) {
            s_rr += __shfl_xor_sync(0xffffffffu, s_rr, off);
            s_ii += __shfl_xor_sync(0xffffffffu, s_ii, off);
            s_ri += __shfl_xor_sync(0xffffffffu, s_ri, off);
            s_ir += __shfl_xor_sync(0xffffffffu, s_ir, off);
        }
        if (lane < 4) {
            cHs[kk * 16 + w]     = s_rr + s_ii + ch_re[(b * 4 + kk) * 8 + w];
            cHs[kk * 16 + 8 + w] = s_ri - s_ir + ch_im[(b * 4 + kk) * 8 + w];
        }
    }
    __syncthreads();

    if (tid < 128) {
        float a = b1_b[tid];
        for (int c = 0; c < 64; c++) a += b1_w[tid * 64 + c] * cHs[c];
        W1s[tid] = fmaxf(a, 0.f);
    } else {
        int jj = tid - 128;
        float a = p1_b[jj];
        for (int c = 0; c < 64; c++) a += p1_w[jj * 64 + c] * cHs[c];
        P1s[jj] = fmaxf(a, 0.f);
    }
    __syncthreads();

    if (tid < 128) {
        float a = b2_b[tid];
        for (int c = 0; c < 128; c++) a += b2_w[tid * 128 + c] * W1s[c];
        W2s[tid] = fmaxf(a, 0.f);
    } else if (tid < 130) {
        int m2 = tid - 128;
        float a = p2_b[m2];
        for (int c = 0; c < 128; c++) a += p2_w[m2 * 128 + c] * P1s[c];
        MUs[m2] = a;
    }
    __syncthreads();

    if (tid < 80) {
        float a = b3_b[tid];
        for (int c = 0; c < 128; c++) a += b3_w[tid * 128 + c] * W2s[c];
        W3s[tid] = a;
    }
    __syncthreads();

    if (tid == 0) {
        float ss = 0.f;
        for (int j = 0; j < 80; j++) ss += W3s[j] * W3s[j];
        float wn = fmaxf(sqrtf(ss), 1e-12f);
        float mx = fmaxf(MUs[0], MUs[1]);
        float e0 = expf(MUs[0] - mx), e1 = expf(MUs[1] - mx);
        float mu0 = e0 / (e0 + e1);
        MUs[0] = mu0;
        MUs[1] = e1 / (e0 + e1);
        SCs[0] = sqrtf(10.0f) * sqrtf(mu0) / wn;
    }
    __syncthreads();

    if (tid < 80) outW[b * 80 + tid] = W3s[tid] * SCs[0];
    if (tid < 2)  outMu[b * 2 + tid] = MUs[tid];
}

// ---------------- launch ----------------
extern "C" void kernel_launch(void* const* d_in, const int* in_sizes, int n_in,
                              void* d_out, int out_size)
{
    const float* x       = (const float*)d_in[0];
    const float* H_re    = (const float*)d_in[1];
    const float* H_im    = (const float*)d_in[2];
    const float* ch_re   = (const float*)d_in[3];
    const float* ch_im   = (const float*)d_in[4];
    const float* conv1_w = (const float*)d_in[5];
    const float* conv1_b = (const float*)d_in[6];
    const float* conv2_w = (const float*)d_in[7];
    const float* conv2_b = (const float*)d_in[8];
    const float* pl1_w   = (const float*)d_in[9];
    const float* pl1_b   = (const float*)d_in[10];
    const float* pl2_w   = (const float*)d_in[11];
    const float* pl2_b   = (const float*)d_in[12];
    const float* b1_w    = (const float*)d_in[13];
    const float* b1_b    = (const float*)d_in[14];
    const float* b2_w    = (const float*)d_in[15];
    const float* b2_b    = (const float*)d_in[16];
    const float* b3_w    = (const float*)d_in[17];
    const float* b3_b    = (const float*)d_in[18];
    const float* p1_w    = (const float*)d_in[19];
    const float* p1_b    = (const float*)d_in[20];
    const float* p2_w    = (const float*)d_in[21];
    const float* p2_b    = (const float*)d_in[22];

    float* out      = (float*)d_out;
    float* outW     = out;
    float* outTheta = out + OFF_THETA;
    float* outMu    = out + OFF_MU;

    cudaFuncSetAttribute(kF, cudaFuncAttributeMaxDynamicSharedMemorySize, KF_DYN);

    k0_transpose<<<128, 256>>>(pl2_w);
    k0x<<<(ROWS * POS) / 256, 256>>>(x);
    dim3 gp(FLAT / 32, JD / 32);
    k0p<<<gp, 256>>>(pl1_w);
    dim3 gp2(POS, 8);
    k0p2<<<gp2, 256>>>();
    dim3 gf(ROWS / 128, SPLIT);
    kF<<<gf, 256, KF_DYN>>>(conv1_w, conv1_b, conv2_w, conv2_b);
    k34<<<B_, 256>>>(pl1_b, pl2_b, H_re, H_im, ch_re, ch_im,
                     b1_w, b1_b, b2_w, b2_b, b3_w, b3_b,
                     p1_w, p1_b, p2_w, p2_b, outW, outTheta, outMu);
}